// round 15
// baseline (speedup 1.0000x reference)
#include <cuda_runtime.h>
#include <cuda_fp16.h>
#include <cstdint>

// ---------------------------------------------------------------------------
// GraphNeuralNetwork: 4 sparse layers, DEG=64 parents per node, B=512.
// Round 15: R14 structure (direct-L2 gather, 4-warp edge split, CTA=1 node)
// + chunked fp16 accumulation: HFMA2 into fp16 partials, flushed to fp32
// every 8 edges. Weights pre-packed as duplicated half2 in the edge record.
// ---------------------------------------------------------------------------

#define BATCH 512

__device__ __align__(16) __half g_hA[2048 * 512];
__device__ __align__(16) __half g_hB[2048 * 512];
__device__ __align__(16) int4   g_pairs[4][2048 * 32];  // {off0, off1, w0h2, w1h2}

// ---------------------------------------------------------------------------
// Fused prep: transpose x (blocks 0..255) + pack edge pairs for all layers.
// offset = src * 1024 (byte offset of row in fp16 [node,batch] buffer);
// weights stored as duplicated fp16 pairs (half2) for HFMA2.
// ---------------------------------------------------------------------------
__device__ __forceinline__ void prep_node_pairs(
    const int* __restrict__ src, const float* __restrict__ w,
    int gw, int lane, int4* __restrict__ ed) {
    int i0 = gw * 64 + 2 * lane;
    int   s0 = src[i0],     s1 = src[i0 + 1];
    float v0 = w[i0];       float v1 = w[i0 + 1];
    __half2 h0 = __half2half2(__float2half(v0));
    __half2 h1 = __half2half2(__float2half(v1));
    ed[gw * 32 + lane] = make_int4(s0 << 10, s1 << 10,
                                   *(int*)&h0, *(int*)&h1);
}

__global__ void fused_prep(
    const float* __restrict__ x, __half* __restrict__ hA,
    const int* __restrict__ src0, const float* __restrict__ w0,
    const int* __restrict__ src1, const float* __restrict__ w1,
    const int* __restrict__ src2, const float* __restrict__ w2,
    const int* __restrict__ src3, const float* __restrict__ w3,
    int4* __restrict__ ed) {
    __shared__ float t[32][33];
    int b   = blockIdx.x;
    int tid = threadIdx.x;

    if (b < 256) {
        // transpose x [512,512] fp32 -> hA [node, batch] fp16
        int bx = (b & 15) * 32, by = (b >> 4) * 32;
        int tx = tid & 31, ty = tid >> 5;       // 32 x 8
#pragma unroll
        for (int i = 0; i < 32; i += 8)
            t[ty + i][tx] = x[(by + ty + i) * 512 + bx + tx];
        __syncthreads();
#pragma unroll
        for (int i = 0; i < 32; i += 8)
            hA[(bx + ty + i) * 512 + by + tx] = __float2half(t[tx][ty + i]);
        return;
    }

    int lane = tid & 31;
    int warp = tid >> 5;                        // 8 warps/block -> 8 nodes/block
    int pb   = b - 256;
    if (pb < 256) {
        prep_node_pairs(src0, w0, pb * 8 + warp, lane, ed);
    } else if (pb < 512) {
        prep_node_pairs(src1, w1, (pb - 256) * 8 + warp, lane, ed + 1 * 2048 * 32);
    } else if (pb < 768) {
        prep_node_pairs(src2, w2, (pb - 512) * 8 + warp, lane, ed + 2 * 2048 * 32);
    } else {  // 64 blocks x 8 warps = 512 nodes
        prep_node_pairs(src3, w3, (pb - 768) * 8 + warp, lane, ed + 3 * 2048 * 32);
    }
}

// ---------------------------------------------------------------------------
// Direct-gather layer kernel, 4-warp split. CTA = 1 node, 8 warps:
//   warp w: grp = w>>2 (256-col half of batch), half = w&3 (16-edge quarter).
// Per warp: 2 chunks of 4 pairs; each chunk accumulates 8 edges in fp16
// (HFMA2), then flushes to fp32. Halves 1-3 publish partials to SMEM;
// half 0 combines, adds bias, writes.
// ---------------------------------------------------------------------------
template <bool RELU, bool FINAL>
__global__ __launch_bounds__(256)
void layer_direct(const __half* __restrict__ h_in,
                  const int4*  __restrict__ pairs,
                  const float* __restrict__ bias,
                  void*        __restrict__ outv) {
    __shared__ float sPart[2][3][256];          // [grp][half-1][i*32 + lane]

    const int tid   = threadIdx.x;
    const int lane  = tid & 31;
    const int wInB  = tid >> 5;                 // 0..7
    const int half  = wInB & 3;
    const int grp   = wInB >> 2;                // 0/1
    const int node  = blockIdx.x;

    // byte base: col = grp*256 + lane*8 (fp16) -> bytes = grp*512 + lane*16
    const char* hb = (const char*)h_in + grp * 512 + lane * 16;
    const int4* ep = pairs + node * 32 + half * 8;

    float a0 = 0.f, a1 = 0.f, a2 = 0.f, a3 = 0.f;
    float a4 = 0.f, a5 = 0.f, a6 = 0.f, a7 = 0.f;

#pragma unroll
    for (int c = 0; c < 2; c++) {               // 2 chunks of 4 pairs (8 edges)
        __half2 c0 = __float2half2_rn(0.f);
        __half2 c1 = __float2half2_rn(0.f);
        __half2 c2 = __float2half2_rn(0.f);
        __half2 c3 = __float2half2_rn(0.f);
#pragma unroll
        for (int k = 0; k < 4; k++) {
            int4 e = __ldg(ep + c * 4 + k);
            uint4 g0 = __ldg((const uint4*)(hb + e.x));   // 8 cols, source row 0
            uint4 g1 = __ldg((const uint4*)(hb + e.y));   // 8 cols, source row 1
            __half2 wa = *(__half2*)&e.z;
            __half2 wb = *(__half2*)&e.w;
            c0 = __hfma2(*(__half2*)&g0.x, wa, c0);
            c1 = __hfma2(*(__half2*)&g0.y, wa, c1);
            c2 = __hfma2(*(__half2*)&g0.z, wa, c2);
            c3 = __hfma2(*(__half2*)&g0.w, wa, c3);
            c0 = __hfma2(*(__half2*)&g1.x, wb, c0);
            c1 = __hfma2(*(__half2*)&g1.y, wb, c1);
            c2 = __hfma2(*(__half2*)&g1.z, wb, c2);
            c3 = __hfma2(*(__half2*)&g1.w, wb, c3);
        }
        float2 t;
        t = __half22float2(c0); a0 += t.x; a1 += t.y;
        t = __half22float2(c1); a2 += t.x; a3 += t.y;
        t = __half22float2(c2); a4 += t.x; a5 += t.y;
        t = __half22float2(c3); a6 += t.x; a7 += t.y;
    }

    if (half != 0) {                            // warps 1-3 of each grp: publish
        float* sp = sPart[grp][half - 1];
        sp[0 * 32 + lane] = a0;
        sp[1 * 32 + lane] = a1;
        sp[2 * 32 + lane] = a2;
        sp[3 * 32 + lane] = a3;
        sp[4 * 32 + lane] = a4;
        sp[5 * 32 + lane] = a5;
        sp[6 * 32 + lane] = a6;
        sp[7 * 32 + lane] = a7;
    }
    __syncthreads();
    if (half != 0) return;

#pragma unroll
    for (int h = 0; h < 3; h++) {
        const float* sp = sPart[grp][h];
        a0 += sp[0 * 32 + lane];
        a1 += sp[1 * 32 + lane];
        a2 += sp[2 * 32 + lane];
        a3 += sp[3 * 32 + lane];
        a4 += sp[4 * 32 + lane];
        a5 += sp[5 * 32 + lane];
        a6 += sp[6 * 32 + lane];
        a7 += sp[7 * 32 + lane];
    }

    float bv = bias[node];
    float v0 = a0 + bv, v1 = a1 + bv, v2 = a2 + bv, v3 = a3 + bv;
    float v4 = a4 + bv, v5 = a5 + bv, v6 = a6 + bv, v7 = a7 + bv;
    if (RELU) {
        v0 = fmaxf(v0, 0.f); v1 = fmaxf(v1, 0.f); v2 = fmaxf(v2, 0.f); v3 = fmaxf(v3, 0.f);
        v4 = fmaxf(v4, 0.f); v5 = fmaxf(v5, 0.f); v6 = fmaxf(v6, 0.f); v7 = fmaxf(v7, 0.f);
    }

    if (!FINAL) {
        __half2 h0 = __floats2half2_rn(v0, v1);
        __half2 h1 = __floats2half2_rn(v2, v3);
        __half2 h2 = __floats2half2_rn(v4, v5);
        __half2 h3 = __floats2half2_rn(v6, v7);
        uint4 pk = make_uint4(*(unsigned*)&h0, *(unsigned*)&h1,
                              *(unsigned*)&h2, *(unsigned*)&h3);
        __half* out = (__half*)outv;
        *(uint4*)(out + (size_t)node * BATCH + grp * 256 + lane * 8) = pk;
    } else {
        // d_out [B, 512] fp32 row-major: out[col * 512 + node]
        float* out = (float*)outv;
        int c = grp * 256 + lane * 8;
        out[(size_t)(c + 0) * 512 + node] = v0;
        out[(size_t)(c + 1) * 512 + node] = v1;
        out[(size_t)(c + 2) * 512 + node] = v2;
        out[(size_t)(c + 3) * 512 + node] = v3;
        out[(size_t)(c + 4) * 512 + node] = v4;
        out[(size_t)(c + 5) * 512 + node] = v5;
        out[(size_t)(c + 6) * 512 + node] = v6;
        out[(size_t)(c + 7) * 512 + node] = v7;
    }
}

// ---------------------------------------------------------------------------
// Host launch
// ---------------------------------------------------------------------------
extern "C" void kernel_launch(void* const* d_in, const int* in_sizes, int n_in,
                              void* d_out, int out_size) {
    (void)n_in; (void)out_size;

    const float* x;
    const float* w[4];
    const float* b[4];
    const int*   src[4];

    if (in_sizes[0] == 2048) {
        // alphabetical metadata order: b0..b3, dst0..dst3, src0..src3, w0..w3, x
        for (int l = 0; l < 4; l++) {
            b[l]   = (const float*)d_in[l];
            src[l] = (const int*)d_in[8 + l];
            w[l]   = (const float*)d_in[12 + l];
        }
        x = (const float*)d_in[16];
    } else if (in_sizes[7] == 32768) {
        // reference-signature order: x, w0,b0, ..., w3,b3, src0,dst0, ...
        x = (const float*)d_in[0];
        for (int l = 0; l < 4; l++) {
            w[l]   = (const float*)d_in[1 + 2 * l];
            b[l]   = (const float*)d_in[2 + 2 * l];
            src[l] = (const int*)d_in[9 + 2 * l];
        }
    } else {
        // setup_inputs dict order: x, (w,b,src,dst) per layer
        x = (const float*)d_in[0];
        for (int l = 0; l < 4; l++) {
            w[l]   = (const float*)d_in[1 + 4 * l];
            b[l]   = (const float*)d_in[2 + 4 * l];
            src[l] = (const int*)d_in[3 + 4 * l];
        }
    }

    __half* hA; __half* hB; int4* ed;
    cudaGetSymbolAddress((void**)&hA, g_hA);
    cudaGetSymbolAddress((void**)&hB, g_hB);
    cudaGetSymbolAddress((void**)&ed, g_pairs);

    // 1) fused: transpose x -> hA (fp16) + pack edge pairs for all layers
    fused_prep<<<1088, 256>>>(x, hA,
                              src[0], w[0], src[1], w[1],
                              src[2], w[2], src[3], w[3],
                              ed);

    // 2) layers. CTA = 1 node (8 warps: 2 col-groups x 4 edge-quarters).
    layer_direct<true, false><<<2048, 256>>>(hA, ed + 0 * 2048 * 32, b[0], hB);
    layer_direct<true, false><<<2048, 256>>>(hB, ed + 1 * 2048 * 32, b[1], hA);
    layer_direct<true, false><<<2048, 256>>>(hA, ed + 2 * 2048 * 32, b[2], hB);
    layer_direct<false, true><<<512, 256>>>(hB, ed + 3 * 2048 * 32, b[3], d_out);
}